// round 6
// baseline (speedup 1.0000x reference)
#include <cuda_runtime.h>
#include <math.h>

// ---------------------------------------------------------------------------
// SelfExpandingGate: N=500000 rows, 40 floats in/out per row.
//   Wq[172][24] : 136 s*s pair features + 36 v.v pair features -> 16 scal + 8 gates
//                 (C_SC, 1/sqrt3 folded in)
//   Wg[8][16][8]: combined (Wsv[u,b,w] + Wvs[b,u,w]) / 16, w-major
// Main kernel: 1 row/thread, scalar FFMA, weights broadcast from SMEM via
// LDS.128. No local-array address-taking (everything register-resident).
// ---------------------------------------------------------------------------

#define NFEAT 172
#define NOUT  24

__device__ float g_Wq[NFEAT * NOUT];   // feature-major, 24 outputs per feature
__device__ float g_Wg[8 * 16 * 8];     // [w][u][b]

__device__ __forceinline__ float sigf(float x) {
    return __fdividef(1.0f, 1.0f + __expf(-x));
}

// ---------------------------------------------------------------------------
// Prep: build combined weights. One block (tiny).
// ---------------------------------------------------------------------------
__global__ void prep_kernel(const float* __restrict__ Wss0,
                            const float* __restrict__ Wvv0,
                            const float* __restrict__ Wss1,
                            const float* __restrict__ Wvv1,
                            const float* __restrict__ Wsv,
                            const float* __restrict__ Wvs) {
    const float CSC  = 0.055901699437494740f;          // 1/sqrt(320)
    const float CSC3 = CSC * 0.57735026918962576f;     // CSC / sqrt(3)
    int tid = threadIdx.x;

    // ss pair features: k = 0..135
    for (int l = tid; l < 136 * 24; l += blockDim.x) {
        int kk = l / 24, j = l % 24;
        int u = 0, r = kk;
        while (r >= 16 - u) { r -= 16 - u; u++; }
        int v = u + r;
        float val;
        if (j < 16) {
            val = Wss0[(u * 16 + v) * 16 + j];
            if (u != v) val += Wss0[(v * 16 + u) * 16 + j];
        } else {
            int w = j - 16;
            val = Wss1[(u * 16 + v) * 8 + w];
            if (u != v) val += Wss1[(v * 16 + u) * 8 + w];
        }
        g_Wq[kk * 24 + j] = val * CSC;
    }
    // vv pair features: k = 136..171
    for (int l = tid; l < 36 * 24; l += blockDim.x) {
        int kk = l / 24, j = l % 24;
        int a = 0, r = kk;
        while (r >= 8 - a) { r -= 8 - a; a++; }
        int b = a + r;
        float val;
        if (j < 16) {
            val = Wvv0[(a * 8 + b) * 16 + j];
            if (a != b) val += Wvv0[(b * 8 + a) * 16 + j];
        } else {
            int w = j - 16;
            val = Wvv1[(a * 8 + b) * 8 + w];
            if (a != b) val += Wvv1[(b * 8 + a) * 8 + w];
        }
        g_Wq[(136 + kk) * 24 + j] = val * CSC3;
    }
    // combined gated weight: [w][u][b]
    for (int l = tid; l < 8 * 16 * 8; l += blockDim.x) {
        int b = l & 7;
        int u = (l >> 3) & 15;
        int w = l >> 7;
        g_Wg[l] = (Wsv[(u * 8 + b) * 8 + w] + Wvs[(b * 16 + u) * 8 + w]) * 0.0625f;
    }
}

// ---------------------------------------------------------------------------
// Main kernel: one row per thread.
// ---------------------------------------------------------------------------
__global__ void __launch_bounds__(256)
seg_kernel(const float* __restrict__ x, float* __restrict__ out,
           int nrows, float silu_c, float sig_c) {
    __shared__ __align__(16) float sWq[NFEAT * NOUT];
    __shared__ __align__(16) float sWg[8 * 16 * 8];

    for (int i = threadIdx.x; i < NFEAT * NOUT; i += blockDim.x) sWq[i] = g_Wq[i];
    for (int i = threadIdx.x; i < 8 * 16 * 8;   i += blockDim.x) sWg[i] = g_Wg[i];
    __syncthreads();

    int row = blockIdx.x * blockDim.x + threadIdx.x;
    if (row >= nrows) return;

    // ---- load row: 40 contiguous floats via float4, no local address-taking ----
    const float4* xr = reinterpret_cast<const float4*>(x + (size_t)row * 40);
    float s[16];
    float v[24];   // v[b*3+i]
    {
        float4 t;
        t = xr[0]; s[0]  = t.x; s[1]  = t.y; s[2]  = t.z; s[3]  = t.w;
        t = xr[1]; s[4]  = t.x; s[5]  = t.y; s[6]  = t.z; s[7]  = t.w;
        t = xr[2]; s[8]  = t.x; s[9]  = t.y; s[10] = t.z; s[11] = t.w;
        t = xr[3]; s[12] = t.x; s[13] = t.y; s[14] = t.z; s[15] = t.w;
        t = xr[4]; v[0]  = t.x; v[1]  = t.y; v[2]  = t.z; v[3]  = t.w;
        t = xr[5]; v[4]  = t.x; v[5]  = t.y; v[6]  = t.z; v[7]  = t.w;
        t = xr[6]; v[8]  = t.x; v[9]  = t.y; v[10] = t.z; v[11] = t.w;
        t = xr[7]; v[12] = t.x; v[13] = t.y; v[14] = t.z; v[15] = t.w;
        t = xr[8]; v[16] = t.x; v[17] = t.y; v[18] = t.z; v[19] = t.w;
        t = xr[9]; v[20] = t.x; v[21] = t.y; v[22] = t.z; v[23] = t.w;
    }

    // ---- quadratic contraction: 172 features -> 24 outputs ----
    float acc[24];
    #pragma unroll
    for (int j = 0; j < 24; j++) acc[j] = 0.0f;

    {
        int k = 0;
        #pragma unroll
        for (int u = 0; u < 16; u++) {
            #pragma unroll
            for (int vv = u; vv < 16; vv++) {
                float f = s[u] * s[vv];
                const float4* w = reinterpret_cast<const float4*>(sWq + k * 24);
                #pragma unroll
                for (int j = 0; j < 6; j++) {
                    float4 wq = w[j];
                    acc[4 * j + 0] = fmaf(f, wq.x, acc[4 * j + 0]);
                    acc[4 * j + 1] = fmaf(f, wq.y, acc[4 * j + 1]);
                    acc[4 * j + 2] = fmaf(f, wq.z, acc[4 * j + 2]);
                    acc[4 * j + 3] = fmaf(f, wq.w, acc[4 * j + 3]);
                }
                k++;
            }
        }
        #pragma unroll
        for (int a = 0; a < 8; a++) {
            #pragma unroll
            for (int b = a; b < 8; b++) {
                float f = v[a * 3 + 0] * v[b * 3 + 0]
                        + v[a * 3 + 1] * v[b * 3 + 1]
                        + v[a * 3 + 2] * v[b * 3 + 2];
                const float4* w = reinterpret_cast<const float4*>(sWq + k * 24);
                #pragma unroll
                for (int j = 0; j < 6; j++) {
                    float4 wq = w[j];
                    acc[4 * j + 0] = fmaf(f, wq.x, acc[4 * j + 0]);
                    acc[4 * j + 1] = fmaf(f, wq.y, acc[4 * j + 1]);
                    acc[4 * j + 2] = fmaf(f, wq.z, acc[4 * j + 2]);
                    acc[4 * j + 3] = fmaf(f, wq.w, acc[4 * j + 3]);
                }
                k++;
            }
        }
    }

    float4* orow = reinterpret_cast<float4*>(out + (size_t)row * 40);

    // ---- epilogue part 1: out_s (scal outputs 0..15) ----
    {
        float4 o;
        o.x = silu_c * acc[0]  * sigf(acc[0]);
        o.y = silu_c * acc[1]  * sigf(acc[1]);
        o.z = silu_c * acc[2]  * sigf(acc[2]);
        o.w = silu_c * acc[3]  * sigf(acc[3]);
        orow[0] = o;
        o.x = silu_c * acc[4]  * sigf(acc[4]);
        o.y = silu_c * acc[5]  * sigf(acc[5]);
        o.z = silu_c * acc[6]  * sigf(acc[6]);
        o.w = silu_c * acc[7]  * sigf(acc[7]);
        orow[1] = o;
        o.x = silu_c * acc[8]  * sigf(acc[8]);
        o.y = silu_c * acc[9]  * sigf(acc[9]);
        o.z = silu_c * acc[10] * sigf(acc[10]);
        o.w = silu_c * acc[11] * sigf(acc[11]);
        orow[2] = o;
        o.x = silu_c * acc[12] * sigf(acc[12]);
        o.y = silu_c * acc[13] * sigf(acc[13]);
        o.z = silu_c * acc[14] * sigf(acc[14]);
        o.w = silu_c * acc[15] * sigf(acc[15]);
        orow[3] = o;
    }

    // ---- gates ----
    float g[8];
    #pragma unroll
    for (int w = 0; w < 8; w++) g[w] = sig_c * sigf(acc[16 + w]);

    // ---- gated bilinear, one w at a time ----
    // gated[w,i] = sum_b ( sum_u s_u Wg[w,u,b] ) * v[b,i]
    float ov[24];
    #pragma unroll
    for (int w = 0; w < 8; w++) {
        float A0 = 0.f, A1 = 0.f, A2 = 0.f, A3 = 0.f;
        float A4 = 0.f, A5 = 0.f, A6 = 0.f, A7 = 0.f;
        #pragma unroll
        for (int u = 0; u < 16; u++) {
            const float4* wr = reinterpret_cast<const float4*>(sWg + (w * 16 + u) * 8);
            float4 p0 = wr[0];
            float4 p1 = wr[1];
            float su = s[u];
            A0 = fmaf(su, p0.x, A0);
            A1 = fmaf(su, p0.y, A1);
            A2 = fmaf(su, p0.z, A2);
            A3 = fmaf(su, p0.w, A3);
            A4 = fmaf(su, p1.x, A4);
            A5 = fmaf(su, p1.y, A5);
            A6 = fmaf(su, p1.z, A6);
            A7 = fmaf(su, p1.w, A7);
        }
        float gw = g[w];
        #pragma unroll
        for (int i = 0; i < 3; i++) {
            float t = A0 * v[0 * 3 + i];
            t = fmaf(A1, v[1 * 3 + i], t);
            t = fmaf(A2, v[2 * 3 + i], t);
            t = fmaf(A3, v[3 * 3 + i], t);
            t = fmaf(A4, v[4 * 3 + i], t);
            t = fmaf(A5, v[5 * 3 + i], t);
            t = fmaf(A6, v[6 * 3 + i], t);
            t = fmaf(A7, v[7 * 3 + i], t);
            ov[w * 3 + i] = gw * t;
        }
    }

    // ---- epilogue part 2: store out_v (24 floats) as 6 float4 ----
    {
        float4 o;
        o.x = ov[0];  o.y = ov[1];  o.z = ov[2];  o.w = ov[3];  orow[4] = o;
        o.x = ov[4];  o.y = ov[5];  o.z = ov[6];  o.w = ov[7];  orow[5] = o;
        o.x = ov[8];  o.y = ov[9];  o.z = ov[10]; o.w = ov[11]; orow[6] = o;
        o.x = ov[12]; o.y = ov[13]; o.z = ov[14]; o.w = ov[15]; orow[7] = o;
        o.x = ov[16]; o.y = ov[17]; o.z = ov[18]; o.w = ov[19]; orow[8] = o;
        o.x = ov[20]; o.y = ov[21]; o.z = ov[22]; o.w = ov[23]; orow[9] = o;
    }
}

// ---------------------------------------------------------------------------
// Host: reproduce reference trapezoid normalization constants (untimed).
// ---------------------------------------------------------------------------
static void compute_constants(double* silu_c, double* sig_c) {
    const int NPT = 200001;
    const double dx = 24.0 / 200000.0;
    const double inv_sqrt2pi = 1.0 / sqrt(2.0 * 3.14159265358979323846);
    double s_silu = 0.0, s_sig = 0.0;
    for (int i = 0; i < NPT; i++) {
        double xv = -12.0 + dx * (double)i;
        double pdf = exp(-0.5 * xv * xv) * inv_sqrt2pi;
        double sg = 1.0 / (1.0 + exp(-xv));
        double si = xv * sg;
        double wgt = (i == 0 || i == NPT - 1) ? 0.5 : 1.0;
        s_silu += wgt * si * si * pdf;
        s_sig  += wgt * sg * sg * pdf;
    }
    s_silu *= dx; s_sig *= dx;
    *silu_c = 1.0 / sqrt(s_silu);
    *sig_c  = 1.0 / sqrt(s_sig);
}

extern "C" void kernel_launch(void* const* d_in, const int* in_sizes, int n_in,
                              void* d_out, int out_size) {
    const float* x    = (const float*)d_in[0];
    const float* Wss0 = (const float*)d_in[1];
    const float* Wvv0 = (const float*)d_in[2];
    const float* Wss1 = (const float*)d_in[3];
    const float* Wvv1 = (const float*)d_in[4];
    const float* Wsv  = (const float*)d_in[5];
    const float* Wvs  = (const float*)d_in[6];
    float* out = (float*)d_out;

    int nrows = in_sizes[0] / 40;

    double sc, gc;
    compute_constants(&sc, &gc);

    prep_kernel<<<1, 256>>>(Wss0, Wvv0, Wss1, Wvv1, Wsv, Wvs);
    int threads = 256;
    int blocks = (nrows + threads - 1) / threads;
    seg_kernel<<<blocks, threads>>>(x, out, nrows, (float)sc, (float)gc);
}

// round 8
// speedup vs baseline: 1.0011x; 1.0011x over previous
#include <cuda_runtime.h>
#include <math.h>

// ---------------------------------------------------------------------------
// SelfExpandingGate: N=500000 rows, 40 floats in/out per row.
//   Wq[172][24]       : symmetrized quadratic weights (C_SC, 1/sqrt3 folded)
//   WgP[4][16][8][2]  : combined (Wsv+Wvs^T)/16 interleaved by w-pair
// seg_kernel: 64 threads/block, 2 rows/thread (128 rows/block).
//   * coalesced global I/O staged through padded SMEM (row stride 44 floats)
//   * weights broadcast from SMEM, loaded once per 2 rows
//   * all heavy FMAs packed as fp32x2 over output pairs
// ---------------------------------------------------------------------------

#define NFEAT 172
#define NOUT  24
#define TPB   64
#define RPB   128          // rows per block
#define RP    44           // padded row stride (floats): 16B-aligned, phase-conflict-free

__device__ float g_Wq[NFEAT * NOUT];      // feature-major
__device__ float g_WgP[4 * 16 * 8 * 2];   // [wp][u][b][lane], w = wp*2+lane

typedef unsigned long long ull;

__device__ __forceinline__ ull pk2s(float f) {          // (f, f)
    ull r; asm("mov.b64 %0,{%1,%1};" : "=l"(r) : "f"(f)); return r;
}
__device__ __forceinline__ void upk2(ull v, float& lo, float& hi) {
    asm("mov.b64 {%0,%1},%2;" : "=f"(lo), "=f"(hi) : "l"(v));
}
__device__ __forceinline__ ull fma2(ull a, ull b, ull c) {
    ull d; asm("fma.rn.f32x2 %0,%1,%2,%3;" : "=l"(d) : "l"(a), "l"(b), "l"(c)); return d;
}
__device__ __forceinline__ float sigf(float x) {
    return __fdividef(1.0f, 1.0f + __expf(-x));
}

// ---------------------------------------------------------------------------
// Prep: build combined weights. One block (tiny, untimed-dominant).
// ---------------------------------------------------------------------------
__global__ void prep_kernel(const float* __restrict__ Wss0,
                            const float* __restrict__ Wvv0,
                            const float* __restrict__ Wss1,
                            const float* __restrict__ Wvv1,
                            const float* __restrict__ Wsv,
                            const float* __restrict__ Wvs) {
    const float CSC  = 0.055901699437494740f;          // 1/sqrt(320)
    const float CSC3 = CSC * 0.57735026918962576f;     // CSC / sqrt(3)
    int tid = threadIdx.x;

    for (int l = tid; l < 136 * 24; l += blockDim.x) {
        int kk = l / 24, j = l % 24;
        int u = 0, r = kk;
        while (r >= 16 - u) { r -= 16 - u; u++; }
        int v = u + r;
        float val;
        if (j < 16) {
            val = Wss0[(u * 16 + v) * 16 + j];
            if (u != v) val += Wss0[(v * 16 + u) * 16 + j];
        } else {
            int w = j - 16;
            val = Wss1[(u * 16 + v) * 8 + w];
            if (u != v) val += Wss1[(v * 16 + u) * 8 + w];
        }
        g_Wq[kk * 24 + j] = val * CSC;
    }
    for (int l = tid; l < 36 * 24; l += blockDim.x) {
        int kk = l / 24, j = l % 24;
        int a = 0, r = kk;
        while (r >= 8 - a) { r -= 8 - a; a++; }
        int b = a + r;
        float val;
        if (j < 16) {
            val = Wvv0[(a * 8 + b) * 16 + j];
            if (a != b) val += Wvv0[(b * 8 + a) * 16 + j];
        } else {
            int w = j - 16;
            val = Wvv1[(a * 8 + b) * 8 + w];
            if (a != b) val += Wvv1[(b * 8 + a) * 8 + w];
        }
        g_Wq[(136 + kk) * 24 + j] = val * CSC3;
    }
    // [wp][u][b][lane], w = wp*2 + lane
    for (int l = tid; l < 4 * 16 * 8 * 2; l += blockDim.x) {
        int lane = l & 1;
        int b = (l >> 1) & 7;
        int u = (l >> 4) & 15;
        int wp = l >> 8;
        int w = wp * 2 + lane;
        g_WgP[l] = (Wsv[(u * 8 + b) * 8 + w] + Wvs[(b * 16 + u) * 8 + w]) * 0.0625f;
    }
}

// ---------------------------------------------------------------------------
// Main kernel.
// ---------------------------------------------------------------------------
__global__ void __launch_bounds__(TPB)
seg_kernel(const float* __restrict__ x, float* __restrict__ out,
           int nrows, float silu_c, float sig_c) {
    __shared__ __align__(16) float sWq[NFEAT * NOUT];       // 16.5 KB
    __shared__ __align__(16) float sWgP[4 * 16 * 8 * 2];    //  4.0 KB
    __shared__ __align__(16) float sbuf[RPB * RP];          // 22.5 KB

    int tid = threadIdx.x;
    for (int i = tid; i < NFEAT * NOUT;   i += TPB) sWq[i]  = g_Wq[i];
    for (int i = tid; i < 4 * 16 * 8 * 2; i += TPB) sWgP[i] = g_WgP[i];

    int base = blockIdx.x * RPB;
    int rows = nrows - base; if (rows > RPB) rows = RPB;
    int n4 = rows * 10;                   // float4 chunks this block

    // ---- cooperative coalesced load into padded SMEM ----
    const float4* gx = reinterpret_cast<const float4*>(x + (size_t)base * 40);
    for (int j = tid; j < n4; j += TPB) {
        float4 t = gx[j];
        int r = j / 10, c = (j % 10) * 4;
        *reinterpret_cast<float4*>(&sbuf[r * RP + c]) = t;
    }
    __syncthreads();

    // ---- pull this thread's 2 rows into registers (conflict-free LDS.128) ----
    float sA[16], vA[24], sB[16], vB[24];
    {
        const float4* rA = reinterpret_cast<const float4*>(&sbuf[tid * RP]);
        const float4* rB = reinterpret_cast<const float4*>(&sbuf[(tid + TPB) * RP]);
        float4 t;
        t = rA[0]; sA[0]=t.x; sA[1]=t.y; sA[2]=t.z; sA[3]=t.w;
        t = rA[1]; sA[4]=t.x; sA[5]=t.y; sA[6]=t.z; sA[7]=t.w;
        t = rA[2]; sA[8]=t.x; sA[9]=t.y; sA[10]=t.z; sA[11]=t.w;
        t = rA[3]; sA[12]=t.x; sA[13]=t.y; sA[14]=t.z; sA[15]=t.w;
        t = rA[4]; vA[0]=t.x; vA[1]=t.y; vA[2]=t.z; vA[3]=t.w;
        t = rA[5]; vA[4]=t.x; vA[5]=t.y; vA[6]=t.z; vA[7]=t.w;
        t = rA[6]; vA[8]=t.x; vA[9]=t.y; vA[10]=t.z; vA[11]=t.w;
        t = rA[7]; vA[12]=t.x; vA[13]=t.y; vA[14]=t.z; vA[15]=t.w;
        t = rA[8]; vA[16]=t.x; vA[17]=t.y; vA[18]=t.z; vA[19]=t.w;
        t = rA[9]; vA[20]=t.x; vA[21]=t.y; vA[22]=t.z; vA[23]=t.w;
        t = rB[0]; sB[0]=t.x; sB[1]=t.y; sB[2]=t.z; sB[3]=t.w;
        t = rB[1]; sB[4]=t.x; sB[5]=t.y; sB[6]=t.z; sB[7]=t.w;
        t = rB[2]; sB[8]=t.x; sB[9]=t.y; sB[10]=t.z; sB[11]=t.w;
        t = rB[3]; sB[12]=t.x; sB[13]=t.y; sB[14]=t.z; sB[15]=t.w;
        t = rB[4]; vB[0]=t.x; vB[1]=t.y; vB[2]=t.z; vB[3]=t.w;
        t = rB[5]; vB[4]=t.x; vB[5]=t.y; vB[6]=t.z; vB[7]=t.w;
        t = rB[6]; vB[8]=t.x; vB[9]=t.y; vB[10]=t.z; vB[11]=t.w;
        t = rB[7]; vB[12]=t.x; vB[13]=t.y; vB[14]=t.z; vB[15]=t.w;
        t = rB[8]; vB[16]=t.x; vB[17]=t.y; vB[18]=t.z; vB[19]=t.w;
        t = rB[9]; vB[20]=t.x; vB[21]=t.y; vB[22]=t.z; vB[23]=t.w;
    }

    // ---- quadratic contraction: 172 features -> 24 outputs (12 f32x2 accs/row) ----
    ull accA[12], accB[12];
    #pragma unroll
    for (int j = 0; j < 12; j++) { accA[j] = 0ull; accB[j] = 0ull; }

    {
        int k = 0;
        #pragma unroll
        for (int u = 0; u < 16; u++) {
            #pragma unroll
            for (int vv = u; vv < 16; vv++) {
                ull fA2 = pk2s(sA[u] * sA[vv]);
                ull fB2 = pk2s(sB[u] * sB[vv]);
                const ulonglong2* w = reinterpret_cast<const ulonglong2*>(sWq + k * 24);
                #pragma unroll
                for (int j = 0; j < 6; j++) {
                    ulonglong2 wq = w[j];
                    accA[2*j]   = fma2(fA2, wq.x, accA[2*j]);
                    accA[2*j+1] = fma2(fA2, wq.y, accA[2*j+1]);
                    accB[2*j]   = fma2(fB2, wq.x, accB[2*j]);
                    accB[2*j+1] = fma2(fB2, wq.y, accB[2*j+1]);
                }
                k++;
            }
        }
        #pragma unroll
        for (int a = 0; a < 8; a++) {
            #pragma unroll
            for (int b = a; b < 8; b++) {
                float fA = vA[a*3+0]*vB[0]*0.0f + vA[a*3+0]*vA[b*3+0]
                         + vA[a*3+1]*vA[b*3+1] + vA[a*3+2]*vA[b*3+2];
                float fB = vB[a*3+0]*vB[b*3+0] + vB[a*3+1]*vB[b*3+1]
                         + vB[a*3+2]*vB[b*3+2];
                ull fA2 = pk2s(fA);
                ull fB2 = pk2s(fB);
                const ulonglong2* w = reinterpret_cast<const ulonglong2*>(sWq + k * 24);
                #pragma unroll
                for (int j = 0; j < 6; j++) {
                    ulonglong2 wq = w[j];
                    accA[2*j]   = fma2(fA2, wq.x, accA[2*j]);
                    accA[2*j+1] = fma2(fA2, wq.y, accA[2*j+1]);
                    accB[2*j]   = fma2(fB2, wq.x, accB[2*j]);
                    accB[2*j+1] = fma2(fB2, wq.y, accB[2*j+1]);
                }
                k++;
            }
        }
    }

    // ---- epilogue 1: out_s to SMEM rows, compute gates ----
    float gA[8], gB[8];
    {
        float q0, q1;
        float* oA = &sbuf[tid * RP];
        float* oB = &sbuf[(tid + TPB) * RP];
        #pragma unroll
        for (int m = 0; m < 8; m++) {          // acc pairs 0..7 -> 16 scal outs
            upk2(accA[m], q0, q1);
            oA[2*m]   = silu_c * q0 * sigf(q0);
            oA[2*m+1] = silu_c * q1 * sigf(q1);
            upk2(accB[m], q0, q1);
            oB[2*m]   = silu_c * q0 * sigf(q0);
            oB[2*m+1] = silu_c * q1 * sigf(q1);
        }
        #pragma unroll
        for (int m = 0; m < 4; m++) {          // acc pairs 8..11 -> 8 gates
            upk2(accA[8+m], q0, q1);
            gA[2*m] = sig_c * sigf(q0); gA[2*m+1] = sig_c * sigf(q1);
            upk2(accB[8+m], q0, q1);
            gB[2*m] = sig_c * sigf(q0); gB[2*m+1] = sig_c * sigf(q1);
        }
    }

    // ---- gated bilinear, per w-pair, both rows together ----
    // gated[w,i] = sum_b ( sum_u s_u WgP[wp,u,b,(w&1)] ) * v[b,i]
    {
        float* oA = &sbuf[tid * RP + 16];
        float* oB = &sbuf[(tid + TPB) * RP + 16];
        #pragma unroll
        for (int wp = 0; wp < 4; wp++) {
            ull AbA[8], AbB[8];
            #pragma unroll
            for (int b = 0; b < 8; b++) { AbA[b] = 0ull; AbB[b] = 0ull; }

            #pragma unroll
            for (int u = 0; u < 16; u++) {
                ull suA = pk2s(sA[u]);
                ull suB = pk2s(sB[u]);
                const ulonglong2* wr =
                    reinterpret_cast<const ulonglong2*>(sWgP + wp * 256 + u * 16);
                #pragma unroll
                for (int m = 0; m < 4; m++) {
                    ulonglong2 p = wr[m];
                    AbA[2*m]   = fma2(suA, p.x, AbA[2*m]);
                    AbA[2*m+1] = fma2(suA, p.y, AbA[2*m+1]);
                    AbB[2*m]   = fma2(suB, p.x, AbB[2*m]);
                    AbB[2*m+1] = fma2(suB, p.y, AbB[2*m+1]);
                }
            }
            #pragma unroll
            for (int i = 0; i < 3; i++) {
                ull tA = 0ull, tB = 0ull;
                #pragma unroll
                for (int b = 0; b < 8; b++) {
                    tA = fma2(AbA[b], pk2s(vA[b*3+i]), tA);
                    tB = fma2(AbB[b], pk2s(vB[b*3+i]), tB);
                }
                float lo, hi;
                upk2(tA, lo, hi);
                oA[(2*wp)*3 + i]   = gA[2*wp]   * lo;
                oA[(2*wp+1)*3 + i] = gA[2*wp+1] * hi;
                upk2(tB, lo, hi);
                oB[(2*wp)*3 + i]   = gB[2*wp]   * lo;
                oB[(2*wp+1)*3 + i] = gB[2*wp+1] * hi;
            }
        }
    }

    __syncthreads();

    // ---- cooperative coalesced store ----
    float4* gy = reinterpret_cast<float4*>(out + (size_t)base * 40);
    for (int j = tid; j < n4; j += TPB) {
        int r = j / 10, c = (j % 10) * 4;
        gy[j] = *reinterpret_cast<const float4*>(&sbuf[r * RP + c]);
    }
}

// ---------------------------------------------------------------------------
// Host: reproduce reference trapezoid normalization constants (untimed).
// ---------------------------------------------------------------------------
static void compute_constants(double* silu_c, double* sig_c) {
    const int NPT = 200001;
    const double dx = 24.0 / 200000.0;
    const double inv_sqrt2pi = 1.0 / sqrt(2.0 * 3.14159265358979323846);
    double s_silu = 0.0, s_sig = 0.0;
    for (int i = 0; i < NPT; i++) {
        double xv = -12.0 + dx * (double)i;
        double pdf = exp(-0.5 * xv * xv) * inv_sqrt2pi;
        double sg = 1.0 / (1.0 + exp(-xv));
        double si = xv * sg;
        double wgt = (i == 0 || i == NPT - 1) ? 0.5 : 1.0;
        s_silu += wgt * si * si * pdf;
        s_sig  += wgt * sg * sg * pdf;
    }
    s_silu *= dx; s_sig *= dx;
    *silu_c = 1.0 / sqrt(s_silu);
    *sig_c  = 1.0 / sqrt(s_sig);
}

extern "C" void kernel_launch(void* const* d_in, const int* in_sizes, int n_in,
                              void* d_out, int out_size) {
    const float* x    = (const float*)d_in[0];
    const float* Wss0 = (const float*)d_in[1];
    const float* Wvv0 = (const float*)d_in[2];
    const float* Wss1 = (const float*)d_in[3];
    const float* Wvv1 = (const float*)d_in[4];
    const float* Wsv  = (const float*)d_in[5];
    const float* Wvs  = (const float*)d_in[6];
    float* out = (float*)d_out;

    int nrows = in_sizes[0] / 40;

    double sc, gc;
    compute_constants(&sc, &gc);

    prep_kernel<<<1, 256>>>(Wss0, Wvv0, Wss1, Wvv1, Wsv, Wvs);
    int blocks = (nrows + RPB - 1) / RPB;
    seg_kernel<<<blocks, TPB>>>(x, out, nrows, (float)sc, (float)gc);
}

// round 9
// speedup vs baseline: 1.0460x; 1.0449x over previous
#include <cuda_runtime.h>
#include <math.h>

// ---------------------------------------------------------------------------
// SelfExpandingGate: N=500000 rows, 40 floats in/out per row.
//   Wq[172][24]       : symmetrized quadratic weights (C_SC, 1/sqrt3 folded)
//   WgP[4][16][8][2]  : combined (Wsv+Wvs^T)/16 interleaved by w-pair
// seg_kernel: 128 threads/block, 1 row/thread.
//   * coalesced global I/O staged through padded SMEM (row stride 44 floats)
//   * weights broadcast from SMEM
//   * all heavy FMAs packed as fp32x2 over output pairs
//   * moderate register footprint (~100) for ~25% occupancy / latency cover
// ---------------------------------------------------------------------------

#define NFEAT 172
#define NOUT  24
#define TPB   128
#define RPB   128          // rows per block (1 per thread)
#define RP    44           // padded row stride (floats): conflict-free LDS.128

__device__ float g_Wq[NFEAT * NOUT];      // feature-major
__device__ float g_WgP[4 * 16 * 8 * 2];   // [wp][u][b][lane], w = wp*2+lane

typedef unsigned long long ull;

__device__ __forceinline__ ull pk2s(float f) {          // (f, f)
    ull r; asm("mov.b64 %0,{%1,%1};" : "=l"(r) : "f"(f)); return r;
}
__device__ __forceinline__ void upk2(ull v, float& lo, float& hi) {
    asm("mov.b64 {%0,%1},%2;" : "=f"(lo), "=f"(hi) : "l"(v));
}
__device__ __forceinline__ ull fma2(ull a, ull b, ull c) {
    ull d; asm("fma.rn.f32x2 %0,%1,%2,%3;" : "=l"(d) : "l"(a), "l"(b), "l"(c)); return d;
}
__device__ __forceinline__ float sigf(float x) {
    return __fdividef(1.0f, 1.0f + __expf(-x));
}

// ---------------------------------------------------------------------------
// Prep: build combined weights. One block (tiny).
// ---------------------------------------------------------------------------
__global__ void prep_kernel(const float* __restrict__ Wss0,
                            const float* __restrict__ Wvv0,
                            const float* __restrict__ Wss1,
                            const float* __restrict__ Wvv1,
                            const float* __restrict__ Wsv,
                            const float* __restrict__ Wvs) {
    const float CSC  = 0.055901699437494740f;          // 1/sqrt(320)
    const float CSC3 = CSC * 0.57735026918962576f;     // CSC / sqrt(3)
    int tid = threadIdx.x;

    for (int l = tid; l < 136 * 24; l += blockDim.x) {
        int kk = l / 24, j = l % 24;
        int u = 0, r = kk;
        while (r >= 16 - u) { r -= 16 - u; u++; }
        int v = u + r;
        float val;
        if (j < 16) {
            val = Wss0[(u * 16 + v) * 16 + j];
            if (u != v) val += Wss0[(v * 16 + u) * 16 + j];
        } else {
            int w = j - 16;
            val = Wss1[(u * 16 + v) * 8 + w];
            if (u != v) val += Wss1[(v * 16 + u) * 8 + w];
        }
        g_Wq[kk * 24 + j] = val * CSC;
    }
    for (int l = tid; l < 36 * 24; l += blockDim.x) {
        int kk = l / 24, j = l % 24;
        int a = 0, r = kk;
        while (r >= 8 - a) { r -= 8 - a; a++; }
        int b = a + r;
        float val;
        if (j < 16) {
            val = Wvv0[(a * 8 + b) * 16 + j];
            if (a != b) val += Wvv0[(b * 8 + a) * 16 + j];
        } else {
            int w = j - 16;
            val = Wvv1[(a * 8 + b) * 8 + w];
            if (a != b) val += Wvv1[(b * 8 + a) * 8 + w];
        }
        g_Wq[(136 + kk) * 24 + j] = val * CSC3;
    }
    // [wp][u][b][lane], w = wp*2 + lane
    for (int l = tid; l < 4 * 16 * 8 * 2; l += blockDim.x) {
        int lane = l & 1;
        int b = (l >> 1) & 7;
        int u = (l >> 4) & 15;
        int wp = l >> 8;
        int w = wp * 2 + lane;
        g_WgP[l] = (Wsv[(u * 8 + b) * 8 + w] + Wvs[(b * 16 + u) * 8 + w]) * 0.0625f;
    }
}

// ---------------------------------------------------------------------------
// Main kernel.
// ---------------------------------------------------------------------------
__global__ void __launch_bounds__(TPB)
seg_kernel(const float* __restrict__ x, float* __restrict__ out,
           int nrows, float silu_c, float sig_c) {
    __shared__ __align__(16) float sWq[NFEAT * NOUT];       // 16.5 KB
    __shared__ __align__(16) float sWgP[4 * 16 * 8 * 2];    //  4.0 KB
    __shared__ __align__(16) float sbuf[RPB * RP];          // 22.5 KB

    int tid = threadIdx.x;
    for (int i = tid; i < NFEAT * NOUT;   i += TPB) sWq[i]  = g_Wq[i];
    for (int i = tid; i < 4 * 16 * 8 * 2; i += TPB) sWgP[i] = g_WgP[i];

    int base = blockIdx.x * RPB;
    int rows = nrows - base; if (rows > RPB) rows = RPB;
    int n4 = rows * 10;                   // float4 chunks this block

    // ---- cooperative coalesced load into padded SMEM ----
    const float4* gx = reinterpret_cast<const float4*>(x + (size_t)base * 40);
    for (int j = tid; j < n4; j += TPB) {
        float4 t = gx[j];
        int r = j / 10, c = (j % 10) * 4;
        *reinterpret_cast<float4*>(&sbuf[r * RP + c]) = t;
    }
    __syncthreads();

    // ---- pull this thread's row into registers (conflict-free LDS.128) ----
    float s[16], v[24];
    {
        const float4* rA = reinterpret_cast<const float4*>(&sbuf[tid * RP]);
        float4 t;
        t = rA[0]; s[0]=t.x; s[1]=t.y; s[2]=t.z; s[3]=t.w;
        t = rA[1]; s[4]=t.x; s[5]=t.y; s[6]=t.z; s[7]=t.w;
        t = rA[2]; s[8]=t.x; s[9]=t.y; s[10]=t.z; s[11]=t.w;
        t = rA[3]; s[12]=t.x; s[13]=t.y; s[14]=t.z; s[15]=t.w;
        t = rA[4]; v[0]=t.x; v[1]=t.y; v[2]=t.z; v[3]=t.w;
        t = rA[5]; v[4]=t.x; v[5]=t.y; v[6]=t.z; v[7]=t.w;
        t = rA[6]; v[8]=t.x; v[9]=t.y; v[10]=t.z; v[11]=t.w;
        t = rA[7]; v[12]=t.x; v[13]=t.y; v[14]=t.z; v[15]=t.w;
        t = rA[8]; v[16]=t.x; v[17]=t.y; v[18]=t.z; v[19]=t.w;
        t = rA[9]; v[20]=t.x; v[21]=t.y; v[22]=t.z; v[23]=t.w;
    }

    // ---- quadratic contraction: 172 features -> 24 outputs (12 f32x2 accs) ----
    ull acc[12];
    #pragma unroll
    for (int j = 0; j < 12; j++) acc[j] = 0ull;

    {
        int k = 0;
        #pragma unroll
        for (int u = 0; u < 16; u++) {
            #pragma unroll
            for (int vv = u; vv < 16; vv++) {
                ull f2 = pk2s(s[u] * s[vv]);
                const ulonglong2* w = reinterpret_cast<const ulonglong2*>(sWq + k * 24);
                #pragma unroll
                for (int j = 0; j < 6; j++) {
                    ulonglong2 wq = w[j];
                    acc[2*j]   = fma2(f2, wq.x, acc[2*j]);
                    acc[2*j+1] = fma2(f2, wq.y, acc[2*j+1]);
                }
                k++;
            }
        }
        #pragma unroll
        for (int a = 0; a < 8; a++) {
            #pragma unroll
            for (int b = a; b < 8; b++) {
                float f = v[a*3+0]*v[b*3+0] + v[a*3+1]*v[b*3+1] + v[a*3+2]*v[b*3+2];
                ull f2 = pk2s(f);
                const ulonglong2* w = reinterpret_cast<const ulonglong2*>(sWq + k * 24);
                #pragma unroll
                for (int j = 0; j < 6; j++) {
                    ulonglong2 wq = w[j];
                    acc[2*j]   = fma2(f2, wq.x, acc[2*j]);
                    acc[2*j+1] = fma2(f2, wq.y, acc[2*j+1]);
                }
                k++;
            }
        }
    }

    // ---- epilogue 1: out_s to SMEM row, compute gates (frees acc) ----
    float g[8];
    {
        float q0, q1;
        float* oA = &sbuf[tid * RP];
        #pragma unroll
        for (int m = 0; m < 8; m++) {          // acc pairs 0..7 -> 16 scal outs
            upk2(acc[m], q0, q1);
            oA[2*m]   = silu_c * q0 * sigf(q0);
            oA[2*m+1] = silu_c * q1 * sigf(q1);
        }
        #pragma unroll
        for (int m = 0; m < 4; m++) {          // acc pairs 8..11 -> 8 gates
            upk2(acc[8+m], q0, q1);
            g[2*m] = sig_c * sigf(q0); g[2*m+1] = sig_c * sigf(q1);
        }
    }

    // ---- gated bilinear, per w-pair ----
    // gated[w,i] = sum_b ( sum_u s_u WgP[wp,u,b,(w&1)] ) * v[b,i]
    {
        float* oA = &sbuf[tid * RP + 16];
        #pragma unroll
        for (int wp = 0; wp < 4; wp++) {
            ull Ab[8];
            #pragma unroll
            for (int b = 0; b < 8; b++) Ab[b] = 0ull;

            #pragma unroll
            for (int u = 0; u < 16; u++) {
                ull su = pk2s(s[u]);
                const ulonglong2* wr =
                    reinterpret_cast<const ulonglong2*>(sWgP + wp * 256 + u * 16);
                #pragma unroll
                for (int m = 0; m < 4; m++) {
                    ulonglong2 p = wr[m];
                    Ab[2*m]   = fma2(su, p.x, Ab[2*m]);
                    Ab[2*m+1] = fma2(su, p.y, Ab[2*m+1]);
                }
            }
            #pragma unroll
            for (int i = 0; i < 3; i++) {
                ull t = 0ull;
                #pragma unroll
                for (int b = 0; b < 8; b++) {
                    t = fma2(Ab[b], pk2s(v[b*3+i]), t);
                }
                float lo, hi;
                upk2(t, lo, hi);
                oA[(2*wp)*3 + i]   = g[2*wp]   * lo;
                oA[(2*wp+1)*3 + i] = g[2*wp+1] * hi;
            }
        }
    }

    __syncthreads();

    // ---- cooperative coalesced store ----
    float4* gy = reinterpret_cast<float4*>(out + (size_t)base * 40);
    for (int j = tid; j < n4; j += TPB) {
        int r = j / 10, c = (j % 10) * 4;
        gy[j] = *reinterpret_cast<const float4*>(&sbuf[r * RP + c]);
    }
}

// ---------------------------------------------------------------------------
// Host: reproduce reference trapezoid normalization constants (untimed).
// ---------------------------------------------------------------------------
static void compute_constants(double* silu_c, double* sig_c) {
    const int NPT = 200001;
    const double dx = 24.0 / 200000.0;
    const double inv_sqrt2pi = 1.0 / sqrt(2.0 * 3.14159265358979323846);
    double s_silu = 0.0, s_sig = 0.0;
    for (int i = 0; i < NPT; i++) {
        double xv = -12.0 + dx * (double)i;
        double pdf = exp(-0.5 * xv * xv) * inv_sqrt2pi;
        double sg = 1.0 / (1.0 + exp(-xv));
        double si = xv * sg;
        double wgt = (i == 0 || i == NPT - 1) ? 0.5 : 1.0;
        s_silu += wgt * si * si * pdf;
        s_sig  += wgt * sg * sg * pdf;
    }
    s_silu *= dx; s_sig *= dx;
    *silu_c = 1.0 / sqrt(s_silu);
    *sig_c  = 1.0 / sqrt(s_sig);
}

extern "C" void kernel_launch(void* const* d_in, const int* in_sizes, int n_in,
                              void* d_out, int out_size) {
    const float* x    = (const float*)d_in[0];
    const float* Wss0 = (const float*)d_in[1];
    const float* Wvv0 = (const float*)d_in[2];
    const float* Wss1 = (const float*)d_in[3];
    const float* Wvv1 = (const float*)d_in[4];
    const float* Wsv  = (const float*)d_in[5];
    const float* Wvs  = (const float*)d_in[6];
    float* out = (float*)d_out;

    int nrows = in_sizes[0] / 40;

    double sc, gc;
    compute_constants(&sc, &gc);

    prep_kernel<<<1, 256>>>(Wss0, Wvv0, Wss1, Wvv1, Wsv, Wvs);
    int blocks = (nrows + RPB - 1) / RPB;
    seg_kernel<<<blocks, TPB>>>(x, out, nrows, (float)sc, (float)gc);
}